// round 15
// baseline (speedup 1.0000x reference)
#include <cuda_runtime.h>

// HEALPix p=1 padding: x (24,128,128,128) f32 -> y (24,128,130,130) f32
// 3072 blocks, one plane each, channel-major remapped (12 consecutive blocks
// = the 12 faces of one (batch,channel) so cross-face gathers hit L2).
// Fully warp-autonomous: each warp owns 16 interior rows; its edge values live
// in its own lanes (shfl-broadcast per row), no smem, no __syncthreads.
// Halo-row gathers hoisted before the store stream; halo stores at the end.

#define NN 128
#define NP 130
#define PLANE_IN  (NN*NN)          // 16384
#define PLANE_OUT (NP*NP)          // 16900
#define FACE_DELTA (128*PLANE_IN)  // 2097152
#define NPLANES 3072

// Per-face neighbor table: t, tl, lft, bl, b, br, rgt, tr
__constant__ int NBT[12][8] = {
    {1, 2, 3, 3, 4, 8, 5, 1},      // F0  north
    {2, 3, 0, 0, 5, 9, 6, 2},      // F1
    {3, 0, 1, 1, 6, 10, 7, 3},     // F2
    {0, 1, 2, 2, 7, 11, 4, 0},     // F3
    {0, -1, 3, 7, 11, -1, 8, 5},   // F4  equatorial
    {1, -1, 0, 4, 8, -1, 9, 6},    // F5
    {2, -1, 1, 5, 9, -1, 10, 7},   // F6
    {3, -1, 2, 6, 10, -1, 11, 4},  // F7
    {5, 0, 4, 11, 11, 10, 9, 9},   // F8  south
    {6, 1, 5, 8, 8, 11, 10, 10},   // F9
    {7, 2, 6, 9, 9, 8, 11, 11},    // F10
    {4, 3, 7, 10, 10, 9, 8, 8},    // F11
};

__device__ __forceinline__ void store_row(
    float* __restrict__ outrow, float4 f4, float lh, float rh, int r, int lane)
{
    if (r & 1) {
        // odd r: aligned 16B chunks at cols [4k+2 .. 4k+5]
        float s = __shfl_down_sync(0xffffffffu, f4.x, 1);   // in[4*lane+4]
        if (lane == 31) s = rh;
        *reinterpret_cast<float4*>(outrow + 4 * lane + 2) =
            make_float4(f4.y, f4.z, f4.w, s);
        if (lane == 0) { outrow[0] = lh; outrow[1] = f4.x; }
    } else {
        // even r: aligned 16B chunks at cols [4k .. 4k+3]
        float s = __shfl_up_sync(0xffffffffu, f4.w, 1);     // in[4*lane-1]
        if (lane == 0) s = lh;
        *reinterpret_cast<float4*>(outrow + 4 * lane) =
            make_float4(s, f4.x, f4.y, f4.z);
        if (lane == 31) { outrow[128] = f4.w; outrow[129] = rh; }
    }
}

// value of the top halo row (output row 0) at column j, for plane base xin
__device__ __forceinline__ float top_halo_val(
    const float* __restrict__ xin, int F, int ty, int j)
{
    int tbase = (NBT[F][0] - F) * FACE_DELTA;
    if (j == 0) {
        if (ty == 0)
            return xin[(NBT[F][1] - F) * FACE_DELTA];                    // tl[0,0]
        if (ty == 1) {
            int lb = (NBT[F][2] - F) * FACE_DELTA;
            return 0.5f * xin[tbase + (NN - 1) * NN]                     // t[127,0]
                 + 0.5f * xin[lb + (NN - 1)];                            // lft[0,127]
        }
        return xin[(NBT[F][1] - F) * FACE_DELTA + (NN - 1) * NN + (NN - 1)]; // tl[127,127]
    }
    if (j == NP - 1)
        return xin[(NBT[F][7] - F) * FACE_DELTA + (NN - 1) * NN];        // tr[127,0]
    int jj = j - 1;
    return (ty == 0) ? xin[tbase + jj * NN]                              // t[jj,0]
                     : xin[tbase + (NN - 1) * NN + jj];                  // t[127,jj]
}

// value of the bottom halo row (output row 129) at column j
__device__ __forceinline__ float bot_halo_val(
    const float* __restrict__ xin, int F, int ty, int j)
{
    int bbase = (NBT[F][4] - F) * FACE_DELTA;
    if (j == 0)
        return xin[(NBT[F][3] - F) * FACE_DELTA + (NN - 1)];             // bl[0,127]
    if (j == NP - 1) {
        if (ty == 0)
            return xin[(NBT[F][5] - F) * FACE_DELTA];                    // br[0,0]
        if (ty == 1) {
            int rb = (NBT[F][6] - F) * FACE_DELTA;
            return 0.5f * xin[bbase + (NN - 1)]                          // b[0,127]
                 + 0.5f * xin[rb + (NN - 1) * NN];                       // rgt[127,0]
        }
        return xin[(NBT[F][5] - F) * FACE_DELTA + (NN - 1) * NN + (NN - 1)]; // br[127,127]
    }
    int jj = j - 1;
    return (ty == 2) ? xin[bbase + jj * NN + (NN - 1)]                   // b[jj,127]
                     : xin[bbase + jj];                                  // b[0,jj]
}

__global__ void __launch_bounds__(256) healpix_pad_kernel(
    const float* __restrict__ x, float* __restrict__ y)
{
    // channel-major remap: consecutive blocks = 12 faces of one (b,chan)
    int idx  = blockIdx.x;                    // 0..3071
    int F    = idx % 12;
    int g    = idx / 12;                      // 0..255 = (b2, chan)
    int P    = ((g >> 7) * 12 + F) * 128 + (g & 127);

    int tid  = threadIdx.x;
    int warp = tid >> 5;
    int lane = tid & 31;
    int ty   = F >> 2;         // 0=north, 1=equatorial, 2=south

    const float* __restrict__ xin = x + (long)P * PLANE_IN;
    float* __restrict__ yout      = y + (long)P * PLANE_OUT;

    int lft_b = (NBT[F][2] - F) * FACE_DELTA;
    int rgt_b = (NBT[F][6] - F) * FACE_DELTA;

    int ir0 = warp * 16;
    const float* base = xin + ir0 * NN + 4 * lane;

    // 8-deep FIFO prologue
    float4 buf[8];
    #pragma unroll
    for (int j = 0; j < 8; ++j)
        buf[j] = *reinterpret_cast<const float4*>(base + j * NN);

    // warp-private edge values: lanes 0-15 hold left edge of rows ir0+lane,
    // lanes 16-31 hold right edge of rows ir0+(lane-16). shfl-broadcast later.
    float ev;
    {
        int ir = ir0 + (lane & 15);
        if (lane < 16)
            ev = xin[(ty == 0) ? (lft_b + ir) : (lft_b + ir * NN + (NN - 1))];
        else
            ev = xin[(ty == 2) ? (rgt_b + (NN - 1) * NN + ir) : (rgt_b + ir * NN)];
    }

    // halo gathers hoisted: loads issued here, stores at the end
    int j0 = (warp & 3) * 32 + lane;          // 0..127 (j0<2 also covers 128,129)
    float hv0, hv1 = 0.0f;
    if (warp < 4) {
        hv0 = top_halo_val(xin, F, ty, j0);
        if (j0 < 2) hv1 = top_halo_val(xin, F, ty, j0 + 128);
    } else {
        hv0 = bot_halo_val(xin, F, ty, j0);
        if (j0 < 2) hv1 = bot_halo_val(xin, F, ty, j0 + 128);
    }

    #pragma unroll
    for (int k = 0; k < 16; ++k) {
        float4 cur = buf[k & 7];
        if (k + 8 < 16)
            buf[k & 7] = *reinterpret_cast<const float4*>(base + (k + 8) * NN);
        float lh = __shfl_sync(0xffffffffu, ev, k);
        float rh = __shfl_sync(0xffffffffu, ev, 16 + k);
        int r = ir0 + k + 1;
        store_row(yout + r * NP, cur, lh, rh, r, lane);
    }

    // halo stores (values already resident in registers)
    {
        float* outrow = (warp < 4) ? yout : (yout + (NP - 1) * NP);
        outrow[j0] = hv0;
        if (j0 < 2) outrow[j0 + 128] = hv1;
    }
}

extern "C" void kernel_launch(void* const* d_in, const int* in_sizes, int n_in,
                              void* d_out, int out_size)
{
    const float* x = (const float*)d_in[0];
    float* y = (float*)d_out;
    healpix_pad_kernel<<<NPLANES, 256>>>(x, y);
}

// round 16
// speedup vs baseline: 1.0837x; 1.0837x over previous
#include <cuda_runtime.h>

// HEALPix p=1 padding: x (24,128,128,128) f32 -> y (24,128,130,130) f32
// 3072 blocks, one plane each, channel-major remapped (12 consecutive blocks
// = the 12 faces of one (batch,channel) so cross-face gathers hit L2).
// Each block: halo-row values gathered into registers EARLY (latency overlaps
// the interior stream), 8 warps x 16 interior rows (8-deep load->store FIFO,
// prologue hoisted above the edge-staging barrier), halo stores at the end.

#define NN 128
#define NP 130
#define PLANE_IN  (NN*NN)          // 16384
#define PLANE_OUT (NP*NP)          // 16900
#define FACE_DELTA (128*PLANE_IN)  // 2097152
#define NPLANES 3072

// Per-face neighbor table: t, tl, lft, bl, b, br, rgt, tr
__constant__ int NBT[12][8] = {
    {1, 2, 3, 3, 4, 8, 5, 1},      // F0  north
    {2, 3, 0, 0, 5, 9, 6, 2},      // F1
    {3, 0, 1, 1, 6, 10, 7, 3},     // F2
    {0, 1, 2, 2, 7, 11, 4, 0},     // F3
    {0, -1, 3, 7, 11, -1, 8, 5},   // F4  equatorial
    {1, -1, 0, 4, 8, -1, 9, 6},    // F5
    {2, -1, 1, 5, 9, -1, 10, 7},   // F6
    {3, -1, 2, 6, 10, -1, 11, 4},  // F7
    {5, 0, 4, 11, 11, 10, 9, 9},   // F8  south
    {6, 1, 5, 8, 8, 11, 10, 10},   // F9
    {7, 2, 6, 9, 9, 8, 11, 11},    // F10
    {4, 3, 7, 10, 10, 9, 8, 8},    // F11
};

__device__ __forceinline__ void store_row(
    float* __restrict__ outrow, float4 f4, float lh, float rh, int r, int lane)
{
    if (r & 1) {
        // odd r: aligned 16B chunks at cols [4k+2 .. 4k+5]
        float s = __shfl_down_sync(0xffffffffu, f4.x, 1);   // in[4*lane+4]
        if (lane == 31) s = rh;
        *reinterpret_cast<float4*>(outrow + 4 * lane + 2) =
            make_float4(f4.y, f4.z, f4.w, s);
        if (lane == 0) { outrow[0] = lh; outrow[1] = f4.x; }
    } else {
        // even r: aligned 16B chunks at cols [4k .. 4k+3]
        float s = __shfl_up_sync(0xffffffffu, f4.w, 1);     // in[4*lane-1]
        if (lane == 0) s = lh;
        *reinterpret_cast<float4*>(outrow + 4 * lane) =
            make_float4(s, f4.x, f4.y, f4.z);
        if (lane == 31) { outrow[128] = f4.w; outrow[129] = rh; }
    }
}

// value of the top halo row (output row 0) at column j, for plane base xin
__device__ __forceinline__ float top_halo_val(
    const float* __restrict__ xin, int F, int ty, int j)
{
    int tbase = (NBT[F][0] - F) * FACE_DELTA;
    if (j == 0) {
        if (ty == 0)
            return xin[(NBT[F][1] - F) * FACE_DELTA];                    // tl[0,0]
        if (ty == 1) {
            int lb = (NBT[F][2] - F) * FACE_DELTA;
            return 0.5f * xin[tbase + (NN - 1) * NN]                     // t[127,0]
                 + 0.5f * xin[lb + (NN - 1)];                            // lft[0,127]
        }
        return xin[(NBT[F][1] - F) * FACE_DELTA + (NN - 1) * NN + (NN - 1)]; // tl[127,127]
    }
    if (j == NP - 1)
        return xin[(NBT[F][7] - F) * FACE_DELTA + (NN - 1) * NN];        // tr[127,0]
    int jj = j - 1;
    return (ty == 0) ? xin[tbase + jj * NN]                              // t[jj,0]
                     : xin[tbase + (NN - 1) * NN + jj];                  // t[127,jj]
}

// value of the bottom halo row (output row 129) at column j
__device__ __forceinline__ float bot_halo_val(
    const float* __restrict__ xin, int F, int ty, int j)
{
    int bbase = (NBT[F][4] - F) * FACE_DELTA;
    if (j == 0)
        return xin[(NBT[F][3] - F) * FACE_DELTA + (NN - 1)];             // bl[0,127]
    if (j == NP - 1) {
        if (ty == 0)
            return xin[(NBT[F][5] - F) * FACE_DELTA];                    // br[0,0]
        if (ty == 1) {
            int rb = (NBT[F][6] - F) * FACE_DELTA;
            return 0.5f * xin[bbase + (NN - 1)]                          // b[0,127]
                 + 0.5f * xin[rb + (NN - 1) * NN];                       // rgt[127,0]
        }
        return xin[(NBT[F][5] - F) * FACE_DELTA + (NN - 1) * NN + (NN - 1)]; // br[127,127]
    }
    int jj = j - 1;
    return (ty == 2) ? xin[bbase + jj * NN + (NN - 1)]                   // b[jj,127]
                     : xin[bbase + jj];                                  // b[0,jj]
}

__global__ void __launch_bounds__(256) healpix_pad_kernel(
    const float* __restrict__ x, float* __restrict__ y)
{
    __shared__ float sl[NN];   // left edge value per input row
    __shared__ float sr[NN];   // right edge value per input row

    // channel-major remap: consecutive blocks = 12 faces of one (b,chan)
    int idx  = blockIdx.x;                    // 0..3071
    int F    = idx % 12;
    int g    = idx / 12;                      // 0..255 = (b2, chan)
    int P    = ((g >> 7) * 12 + F) * 128 + (g & 127);

    int tid  = threadIdx.x;
    int warp = tid >> 5;
    int lane = tid & 31;
    int ty   = F >> 2;         // 0=north, 1=equatorial, 2=south

    const float* __restrict__ xin = x + (long)P * PLANE_IN;
    float* __restrict__ yout      = y + (long)P * PLANE_OUT;

    int lft_b = (NBT[F][2] - F) * FACE_DELTA;
    int rgt_b = (NBT[F][6] - F) * FACE_DELTA;

    int ir0 = warp * 16;
    const float* base = xin + ir0 * NN + 4 * lane;

    // 8-deep FIFO prologue — issued before the barrier
    float4 buf[8];
    #pragma unroll
    for (int j = 0; j < 8; ++j)
        buf[j] = *reinterpret_cast<const float4*>(base + j * NN);

    // stage edge columns: 128 threads each side, all loads in flight
    if (tid < NN) {
        int ir = tid;
        sl[ir] = xin[(ty == 0) ? (lft_b + ir) : (lft_b + ir * NN + (NN - 1))];
    } else {
        int ir = tid - NN;
        sr[ir] = xin[(ty == 2) ? (rgt_b + (NN - 1) * NN + ir) : (rgt_b + ir * NN)];
    }

    // -------- halo gathers hoisted: loads issued here, stores at the end ----
    int j0 = (warp & 3) * 32 + lane;          // 0..127 (j0<2 also covers 128,129)
    float hv0, hv1 = 0.0f;
    if (warp < 4) {
        hv0 = top_halo_val(xin, F, ty, j0);
        if (j0 < 2) hv1 = top_halo_val(xin, F, ty, j0 + 128);
    } else {
        hv0 = bot_halo_val(xin, F, ty, j0);
        if (j0 < 2) hv1 = bot_halo_val(xin, F, ty, j0 + 128);
    }
    __syncthreads();

    #pragma unroll
    for (int k = 0; k < 16; ++k) {
        float4 cur = buf[k & 7];
        if (k + 8 < 16)
            buf[k & 7] = *reinterpret_cast<const float4*>(base + (k + 8) * NN);
        int ir = ir0 + k;
        int r  = ir + 1;
        store_row(yout + r * NP, cur, sl[ir], sr[ir], r, lane);
    }

    // -------- halo stores (values already resident in registers) ----
    {
        float* outrow = (warp < 4) ? yout : (yout + (NP - 1) * NP);
        outrow[j0] = hv0;
        if (j0 < 2) outrow[j0 + 128] = hv1;
    }
}

extern "C" void kernel_launch(void* const* d_in, const int* in_sizes, int n_in,
                              void* d_out, int out_size)
{
    const float* x = (const float*)d_in[0];
    float* y = (float*)d_out;
    healpix_pad_kernel<<<NPLANES, 256>>>(x, y);
}